// round 16
// baseline (speedup 1.0000x reference)
#include <cuda_runtime.h>
#include <float.h>
#include <cstdint>

#define NCH       36
#define NANCH     8400
#define NCLS      32
#define MAXDET    100
#define BATCH     64
#define NTHREADS  512
#define CLUSTER   2
#define HALF_ANCH 4200            // anchors per CTA
#define KPT       9               // ceil(4200/512)
#define NW        8               // batch width (top-8 per round)
#define CONF_T    0.25f
// iou > 0.45  <=>  inter > (0.45/1.45)*(A+B)   [valid: inter>0 => union>0]
#define C_HI      0.31034523f     // c*(1+~1.3e-6)
#define C_LO      0.31034442f     // c*(1-~1.3e-6)

// dynamic smem per CTA: float4 box[4200] + area[4200] + cls[4200]
#define SMEM_BYTES ((4 + 1 + 1) * HALF_ANCH * 4)

struct alignas(16) Rec {            // winner record (broadcast-read only)
    float y1, x1, y2, x2;
    float area, cls;
    float p0, p1;
};

__device__ __forceinline__ uint32_t smem_u32(const void* p) {
    uint32_t a;
    asm("{ .reg .u64 t; cvta.to.shared.u64 t, %1; cvt.u32.u64 %0, t; }" : "=r"(a) : "l"(p));
    return a;
}
__device__ __forceinline__ uint32_t mapa_u32(uint32_t a, uint32_t rank) {
    uint32_t o;
    asm("mapa.shared::cluster.u32 %0, %1, %2;" : "=r"(o) : "r"(a), "r"(rank));
    return o;
}
__device__ __forceinline__ void st_cluster(uint32_t a, unsigned v) {
    asm volatile("st.shared::cluster.u32 [%0], %1;" :: "r"(a), "r"(v) : "memory");
}
// monotone float -> u32 key (bigger float => bigger key); fkey(0.0f)=0x80000000
__device__ __forceinline__ unsigned fkey(float f) {
    unsigned b = __float_as_uint(f);
    return ((int)b >= 0) ? (b | 0x80000000u) : ~b;
}
__device__ __forceinline__ bool lexGT(uint2 a, uint2 b) {
    return (a.x > b.x) || (a.x == b.x && a.y < b.y);
}
// exact suppression decision: winner (wb, wa) vs anchor (b, ab); winner area first
__device__ __forceinline__ bool kill_test(float4 wb, float wa, float4 b, float ab) {
    float yy1 = fmaxf(wb.x, b.x);
    float xx1 = fmaxf(wb.y, b.y);
    float yy2 = fminf(wb.z, b.z);
    float xx2 = fminf(wb.w, b.w);
    float inter = fmaxf(yy2 - yy1, 0.0f) * fmaxf(xx2 - xx1, 0.0f);
    float S = wa + ab;
    bool kill = inter > C_HI * S;
    if (!kill && !(inter < C_LO * S)) {
        float uni = wa + ab - inter;   // exact reference sequence
        if (uni > 0.0f) kill = (inter / uni) > 0.45f;
    }
    return kill;
}

__global__ __launch_bounds__(NTHREADS, 1) __cluster_dims__(CLUSTER, 1, 1)
void yolo_nms_kernel(const float* __restrict__ in, float* __restrict__ out) {
    extern __shared__ float smem[];
    float4* sbox  = (float4*)smem;             // [4200]
    float*  sarea = smem + 4 * HALF_ANCH;      // [4200]
    float*  scls  = smem + 5 * HALF_ANCH;      // [4200]
    __shared__ uint2 ckey[2][NW * 32];         // parity x (8 winners x 32 warp-slots)
    __shared__ Rec   crec[2][NW * 32];
    __shared__ unsigned long long cbar;        // mbarrier, 256 arrivals/phase

    const int tid  = threadIdx.x;
    const int lane = tid & 31;
    const int wid  = tid >> 5;
    unsigned rank;
    asm("mov.u32 %0, %%cluster_ctarank;" : "=r"(rank));
    const int img   = blockIdx.x >> 1;
    const int gbase = rank * HALF_ANCH;

    const float* base = in + (size_t)img * NCH * NANCH;

    float* ob  = out + (size_t)img * MAXDET * 4;
    float* oc  = out + (size_t)BATCH * MAXDET * 4 + (size_t)img * MAXDET;
    float* osc = out + (size_t)BATCH * MAXDET * 4 + (size_t)BATCH * MAXDET + (size_t)img * MAXDET;
    float* ond = out + (size_t)BATCH * MAXDET * 4 + (size_t)BATCH * MAXDET * 2;

    const uint32_t bar_a  = smem_u32(&cbar);
    const uint32_t peer   = rank ^ 1u;
    const uint32_t r_bar  = mapa_u32(bar_a, peer);
    const uint32_t r_ckey = mapa_u32(smem_u32(&ckey[0][0]), peer);
    const uint32_t r_crec = mapa_u32(smem_u32(&crec[0][0]), peer);

    if (tid == 0) {
        asm volatile("mbarrier.init.shared.b64 [%0], %1;" :: "r"(bar_a), "r"(256u) : "memory");
    }

    if (rank == 0) {
        for (int i = tid; i < MAXDET * 4; i += NTHREADS) ob[i] = 0.0f;
        if (tid < MAXDET) { oc[tid] = 0.0f; osc[tid] = 0.0f; }
    }

    // ---- Phase 1: preprocess this CTA's 4200 anchors ----
    unsigned ukey[KPT];
    #pragma unroll
    for (int k = 0; k < KPT; k++) {
        int l = tid + k * NTHREADS;
        unsigned ku = 0u;
        if (l < HALF_ANCH) {
            int ga = gbase + l;
            float xc = base[0 * NANCH + ga];
            float yc = base[1 * NANCH + ga];
            float w  = base[2 * NANCH + ga];
            float h  = base[3 * NANCH + ga];
            float best = -FLT_MAX;
            int cls = 0;
            #pragma unroll
            for (int c = 0; c < NCLS; c++) {
                float v = base[(4 + c) * NANCH + ga];
                if (v > best) { best = v; cls = c; }   // strict > == first-max
            }
            float y1 = fminf(fmaxf(yc - 0.5f * h, 0.0f), 1.0f);
            float x1 = fminf(fmaxf(xc - 0.5f * w, 0.0f), 1.0f);
            float y2 = fminf(fmaxf(yc + 0.5f * h, 0.0f), 1.0f);
            float x2 = fminf(fmaxf(xc + 0.5f * w, 0.0f), 1.0f);
            sbox[l]  = make_float4(y1, x1, y2, x2);
            sarea[l] = (y2 - y1) * (x2 - x1);
            scls[l]  = (float)cls;
            if (best >= CONF_T) ku = fkey(best);   // masked anchors stay dead (ref: -1)
        }
        ukey[k] = ku;
    }
    __syncthreads();
    asm volatile("barrier.cluster.arrive.aligned;" ::: "memory");
    asm volatile("barrier.cluster.wait.aligned;"   ::: "memory");

    int ndet = 0, d = 0;
    for (int e = 0; e < MAXDET && d < MAXDET; e++) {
        const int p = e & 1;

        // ---- stage 1: per-warp top-8 via iterated redux (key desc, gid asc) ----
        unsigned tk[KPT];
        #pragma unroll
        for (int k = 0; k < KPT; k++) tk[k] = ukey[k];

        unsigned l2k = 0u; int l2i = gbase + tid; int l2w = 0;
        #pragma unroll
        for (int k = KPT - 1; k >= 0; k--) {
            int gid = gbase + tid + k * NTHREADS;
            if (tk[k] >= l2k) { l2k = tk[k]; l2i = gid; l2w = k; }
        }

        unsigned kk[NW], gg[NW];
        #pragma unroll
        for (int j = 0; j < NW; j++) {
            kk[j] = __reduce_max_sync(0xFFFFFFFFu, l2k);
            unsigned cc = (l2k == kk[j]) ? (unsigned)l2i : 0xFFFFFFFFu;
            gg[j] = __reduce_min_sync(0xFFFFFFFFu, cc);
            if (kk[j] != 0u && l2k == kk[j] && (unsigned)l2i == gg[j]) {
                #pragma unroll
                for (int k = 0; k < KPT; k++) if (k == l2w) tk[k] = 0u;
                l2k = 0u; l2i = gbase + tid; l2w = 0;
                #pragma unroll
                for (int k = KPT - 1; k >= 0; k--) {
                    int gid = gbase + tid + k * NTHREADS;
                    if (tk[k] >= l2k) { l2k = tk[k]; l2i = gid; l2w = k; }
                }
            }
        }

        // ---- publish: lanes 0..7 each publish one candidate to BOTH CTAs ----
        unsigned myK = 0u, myG = 0u;
        #pragma unroll
        for (int j = 0; j < NW; j++) if (lane == j) { myK = kk[j]; myG = gg[j]; }
        if (lane < NW) {
            int l = (int)myG - gbase;
            if ((unsigned)l >= HALF_ANCH) l = 0;   // dead-entry clamp; data unused
            float4 bx = sbox[l]; float aa = sarea[l]; float cl2 = scls[l];
            int slot = lane * 32 + (int)rank * 16 + wid;
            ckey[p][slot] = make_uint2(myK, myG);
            Rec r; r.y1 = bx.x; r.x1 = bx.y; r.y2 = bx.z; r.x2 = bx.w;
            r.area = aa; r.cls = cl2; r.p0 = 0.f; r.p1 = 0.f;
            crec[p][slot] = r;
            uint32_t rk = r_ckey + (uint32_t)(p * (NW * 32) + slot) * 8u;
            st_cluster(rk + 0, myK);
            st_cluster(rk + 4, myG);
            uint32_t rr = r_crec + (uint32_t)(p * (NW * 32) + slot) * 32u;
            st_cluster(rr + 0,  __float_as_uint(bx.x));
            st_cluster(rr + 4,  __float_as_uint(bx.y));
            st_cluster(rr + 8,  __float_as_uint(bx.z));
            st_cluster(rr + 12, __float_as_uint(bx.w));
            st_cluster(rr + 16, __float_as_uint(aa));
            st_cluster(rr + 20, __float_as_uint(cl2));
            // per-lane arrives: release orders THIS lane's stores
            asm volatile("mbarrier.arrive.shared.b64 _, [%0];" :: "r"(bar_a) : "memory");
            asm volatile("mbarrier.arrive.release.cluster.shared::cluster.b64 _, [%0];"
                         :: "r"(r_bar) : "memory");
        }

        // ---- wait: 256 arrivals (128 local + 128 remote) ----
        {
            unsigned done;
            asm volatile(
                "{\n\t.reg .pred q;\n\t"
                "mbarrier.try_wait.parity.acquire.cluster.shared::cta.b64 q, [%1], %2, 0x989680;\n\t"
                "selp.b32 %0, 1, 0, q;\n\t}"
                : "=r"(done) : "r"(bar_a), "r"((unsigned)p) : "memory");
            if (!done) {
                asm volatile(
                    "{\n\t.reg .pred Q1;\n\t"
                    "WL_%=:\n\t"
                    "mbarrier.try_wait.parity.acquire.cluster.shared::cta.b64 Q1, [%0], %1, 0x989680;\n\t"
                    "@Q1 bra.uni WD_%=;\n\t"
                    "bra.uni WL_%=;\n\t"
                    "WD_%=:\n\t}"
                    :: "r"(bar_a), "r"((unsigned)p) : "memory");
            }
        }

        // ---- stage 2: global top-8 of 256 candidates (8/lane) ----
        uint2 q[NW];
        #pragma unroll
        for (int j = 0; j < NW; j++) q[j] = ckey[p][lane + 32 * j];

        unsigned K[NW], G[NW]; int S[NW];
        #pragma unroll
        for (int j = 0; j < NW; j++) {
            uint2 lb = q[0]; int lm = 0;
            #pragma unroll
            for (int m = 1; m < NW; m++) if (lexGT(q[m], lb)) { lb = q[m]; lm = m; }
            K[j] = __reduce_max_sync(0xFFFFFFFFu, lb.x);
            unsigned cg = (lb.x == K[j]) ? lb.y : 0xFFFFFFFFu;
            G[j] = __reduce_min_sync(0xFFFFFFFFu, cg);
            bool hit = (lb.x == K[j]) && (lb.y == G[j]);
            unsigned bm = __ballot_sync(0xFFFFFFFFu, hit);
            int selLane = __ffs(bm) - 1;
            int ls2 = lane + 32 * lm;
            S[j] = __shfl_sync(0xFFFFFFFFu, ls2, selLane);
            if (hit && lane == selLane) {
                #pragma unroll
                for (int m = 0; m < NW; m++)
                    if (m == lm) q[m] = make_uint2(0u, 0xFFFFFFFFu);
            }
        }

        if (K[0] <= 0x80000000u) break;   // no positive score anywhere (uniform)

        // load all 8 winner records (broadcast LDS)
        float4 wb[NW]; float wa[NW]; float wc[NW];
        #pragma unroll
        for (int j = 0; j < NW; j++) {
            Rec r = crec[p][S[j]];
            wb[j] = make_float4(r.y1, r.x1, r.y2, r.x2);
            wa[j] = r.area; wc[j] = r.cls;
        }

        // ---- greedy-prefix emission over sorted top-8 (exact arithmetic) ----
        unsigned emask = 1u;
        int cnt = 1;
        #pragma unroll
        for (int j = 1; j < NW; j++) {
            if (K[j] > 0x80000000u && d + cnt < MAXDET) {
                bool kd = false;
                #pragma unroll
                for (int i = 0; i < j; i++)
                    if (emask & (1u << i)) kd = kd || kill_test(wb[i], wa[i], wb[j], wa[j]);
                if (!kd) { emask |= 1u << j; cnt++; }
            }
        }
        ndet += cnt;

        if (rank == 0 && tid == 0) {
            int dd = d;
            #pragma unroll
            for (int j = 0; j < NW; j++) {
                if (emask & (1u << j)) {
                    float s = (K[j] & 0x80000000u) ? __uint_as_float(K[j] & 0x7FFFFFFFu)
                                                   : __uint_as_float(~K[j]);
                    ob[dd * 4 + 0] = wb[j].x; ob[dd * 4 + 1] = wb[j].y;
                    ob[dd * 4 + 2] = wb[j].z; ob[dd * 4 + 3] = wb[j].w;
                    oc[dd] = wc[j]; osc[dd] = s;
                    dd++;
                }
            }
        }

        d += cnt;
        if (d >= MAXDET) break;   // uniform; no pass needed

        // inert-ify non-emitted candidates (kill nothing: inter=0, no div path)
        #pragma unroll
        for (int j = 1; j < NW; j++) {
            if (!(emask & (1u << j))) { wb[j] = make_float4(2.f, 2.f, 2.f, 2.f); wa[j] = 0.f; }
        }

        // owner kills for emitted anchors (pow2 threads: owner tid = l & 511)
        #pragma unroll
        for (int j = 0; j < NW; j++) {
            if (emask & (1u << j)) {
                int l = (int)G[j] - gbase;
                if ((unsigned)l < HALF_ANCH && (l & (NTHREADS - 1)) == tid) {
                    int kw = l >> 9;
                    #pragma unroll
                    for (int k = 0; k < KPT; k++) if (k == kw) ukey[k] = 0u;
                }
            }
        }

        // ---- suppress sub-pass A: winners 0..3 ----
        #pragma unroll
        for (int k = 0; k < KPT; k++) {
            unsigned ku = ukey[k];
            if (ku != 0u) {
                int l = tid + k * NTHREADS;
                float4 b  = sbox[l];
                float  ab = sarea[l];
                bool kl = kill_test(wb[0], wa[0], b, ab);
                kl = kl | kill_test(wb[1], wa[1], b, ab);
                kl = kl | kill_test(wb[2], wa[2], b, ab);
                kl = kl | kill_test(wb[3], wa[3], b, ab);
                if (kl) ukey[k] = 0u;
            }
        }
        // ---- suppress sub-pass B: winners 4..7 (skip if none emitted) ----
        if (emask & 0xF0u) {
            #pragma unroll
            for (int k = 0; k < KPT; k++) {
                unsigned ku = ukey[k];
                if (ku != 0u) {
                    int l = tid + k * NTHREADS;
                    float4 b  = sbox[l];
                    float  ab = sarea[l];
                    bool kl = kill_test(wb[4], wa[4], b, ab);
                    kl = kl | kill_test(wb[5], wa[5], b, ab);
                    kl = kl | kill_test(wb[6], wa[6], b, ab);
                    kl = kl | kill_test(wb[7], wa[7], b, ab);
                    if (kl) ukey[k] = 0u;
                }
            }
        }
    }

    if (rank == 0 && tid == 0) ond[img] = (float)ndet;

    asm volatile("barrier.cluster.arrive.aligned;" ::: "memory");
    asm volatile("barrier.cluster.wait.aligned;"   ::: "memory");
}

extern "C" void kernel_launch(void* const* d_in, const int* in_sizes, int n_in,
                              void* d_out, int out_size) {
    static bool attr_done = false;
    if (!attr_done) {
        cudaFuncSetAttribute(yolo_nms_kernel,
                             cudaFuncAttributeMaxDynamicSharedMemorySize, SMEM_BYTES);
        attr_done = true;
    }
    const float* in = (const float*)d_in[0];
    float* out = (float*)d_out;
    yolo_nms_kernel<<<BATCH * CLUSTER, NTHREADS, SMEM_BYTES>>>(in, out);
}